// round 5
// baseline (speedup 1.0000x reference)
#include <cuda_runtime.h>

// PositionBias: out[b,i0,i1,n] = x[b,i0,i1,n] + bias[min(|s_b - i0 + i1|, 127), n]
//   x: [8,256,256,64] f32 (134 MB), crop_x/crop_y: [8,2] i32, bias: [128,64] f32 (32 KB)
//   s_b = crop_x[b,0] - crop_y[b,0]
// Pure HBM-bound streaming add: 268 MB traffic -> ~38 us floor at ~6300 B/cyc LTS cap.
// float4-vectorized, coalesced, 4 independent front-batched loads/thread (MLP_p1=4).
// Block tile = 1024 float4 = 64 positions: never crosses an i0 or batch boundary,
// so b, i0, s are block-uniform and hoisted.

#define B_DIM 8
#define C_DIM 256               // Cx == Cy == 256
#define NBINS 64
#define F4_PER_POS (NBINS / 4)  // 16 float4 per (b,i0,i1)
#define IDX_CLAMP 127           // bias_size - 1
#define UNROLL 4
#define THREADS 256

__device__ __forceinline__ float4 f4add(float4 a, float4 b) {
    float4 o; o.x = a.x + b.x; o.y = a.y + b.y; o.z = a.z + b.z; o.w = a.w + b.w;
    return o;
}

__global__ void __launch_bounds__(THREADS)
position_bias_kernel(const float4* __restrict__ x,
                     const int*    __restrict__ crop_x,
                     const int*    __restrict__ crop_y,
                     const float4* __restrict__ bias,
                     float4*       __restrict__ out)
{
    // Block-uniform scalars: base position of this tile.
    unsigned posbase = blockIdx.x * (UNROLL * THREADS / F4_PER_POS);   // blockIdx.x * 64
    unsigned i0 = (posbase >> 8) & (C_DIM - 1);
    unsigned bb = posbase >> 16;
    int s = __ldg(&crop_x[2 * bb]) - __ldg(&crop_y[2 * bb]);
    int s0 = s - (int)i0;                       // d = s0 + i1

    unsigned base = blockIdx.x * (UNROLL * THREADS) + threadIdx.x;

    // Front-batched independent global loads (coalesced, MLP = 4).
    float4 xv[UNROLL];
    unsigned g[UNROLL];
#pragma unroll
    for (int u = 0; u < UNROLL; u++) {
        g[u]  = base + u * THREADS;
        xv[u] = x[g[u]];
    }

    float4 r[UNROLL];
#pragma unroll
    for (int u = 0; u < UNROLL; u++) {
        unsigned f  = g[u] & (F4_PER_POS - 1);
        unsigned i1 = (g[u] >> 4) & (C_DIM - 1);
        int idx = min(abs(s0 + (int)i1), IDX_CLAMP);
        float4 bv = __ldg(&bias[idx * F4_PER_POS + f]);
        r[u] = f4add(xv[u], bv);
    }

#pragma unroll
    for (int u = 0; u < UNROLL; u++)
        out[g[u]] = r[u];
}

extern "C" void kernel_launch(void* const* d_in, const int* in_sizes, int n_in,
                              void* d_out, int out_size)
{
    const float4* x      = (const float4*)d_in[0];
    const int*    crop_x = (const int*)d_in[1];
    const int*    crop_y = (const int*)d_in[2];
    const float4* bias   = (const float4*)d_in[3];
    float4*       out    = (float4*)d_out;

    // total float4 = 8*256*256*16 = 8,388,608 ; tile = 1024 -> 8192 blocks, exact cover.
    const int total4 = (B_DIM * C_DIM * C_DIM * NBINS) / 4;
    const int blocks = total4 / (UNROLL * THREADS);

    position_bias_kernel<<<blocks, THREADS>>>(x, crop_x, crop_y, bias, out);
}

// round 6
// speedup vs baseline: 1.0654x; 1.0654x over previous
#include <cuda_runtime.h>

// PositionBias: out[b,i0,i1,n] = x[b,i0,i1,n] + bias[min(|s_b - i0 + i1|, 127), n]
//   x: [8,256,256,64] f32 (134 MB), crop_x/crop_y: [8,2] i32, bias: [128,64] f32 (32 KB)
// R5 baseline: UNROLL4, 46.4us, DRAM 74.9%. This round: UNROLL8 front-batched
// (2x per-warp MLP) + streaming cache hints (__ldcs on x, __stcs on out) to close
// the gap to the ~6.8-7 TB/s HBM ceiling.

#define B_DIM 8
#define C_DIM 256               // Cx == Cy == 256
#define NBINS 64
#define F4_PER_POS (NBINS / 4)  // 16 float4 per (b,i0,i1)
#define IDX_CLAMP 127           // bias_size - 1
#define UNROLL 8
#define THREADS 256

__device__ __forceinline__ float4 f4add(float4 a, float4 b) {
    float4 o; o.x = a.x + b.x; o.y = a.y + b.y; o.z = a.z + b.z; o.w = a.w + b.w;
    return o;
}

__global__ void __launch_bounds__(THREADS)
position_bias_kernel(const float4* __restrict__ x,
                     const int*    __restrict__ crop_x,
                     const int*    __restrict__ crop_y,
                     const float4* __restrict__ bias,
                     float4*       __restrict__ out)
{
    // Block tile = UNROLL*THREADS = 2048 float4 = 128 positions: never crosses an
    // i0 (128 | 256) or batch boundary, so b, i0, s are block-uniform.
    unsigned posbase = blockIdx.x * (UNROLL * THREADS / F4_PER_POS);   // blockIdx.x * 128
    unsigned i0 = (posbase >> 8) & (C_DIM - 1);
    unsigned bb = posbase >> 16;
    int s  = __ldg(&crop_x[2 * bb]) - __ldg(&crop_y[2 * bb]);
    int s0 = s - (int)i0;                        // d = s0 + i1

    unsigned base = blockIdx.x * (UNROLL * THREADS) + threadIdx.x;

    // Front-batched independent streaming loads (coalesced, MLP = 8).
    float4 xv[UNROLL];
#pragma unroll
    for (int u = 0; u < UNROLL; u++)
        xv[u] = __ldcs(&x[base + u * THREADS]);

#pragma unroll
    for (int u = 0; u < UNROLL; u++) {
        unsigned g  = base + u * THREADS;
        unsigned f  = g & (F4_PER_POS - 1);
        unsigned i1 = (g >> 4) & (C_DIM - 1);
        int idx = min(abs(s0 + (int)i1), IDX_CLAMP);
        float4 bv = __ldg(&bias[idx * F4_PER_POS + f]);
        __stcs(&out[g], f4add(xv[u], bv));
    }
}

extern "C" void kernel_launch(void* const* d_in, const int* in_sizes, int n_in,
                              void* d_out, int out_size)
{
    const float4* x      = (const float4*)d_in[0];
    const int*    crop_x = (const int*)d_in[1];
    const int*    crop_y = (const int*)d_in[2];
    const float4* bias   = (const float4*)d_in[3];
    float4*       out    = (float4*)d_out;

    // total float4 = 8*256*256*16 = 8,388,608 ; tile = 2048 -> 4096 blocks, exact cover.
    const int total4 = (B_DIM * C_DIM * C_DIM * NBINS) / 4;
    const int blocks = total4 / (UNROLL * THREADS);

    position_bias_kernel<<<blocks, THREADS>>>(x, crop_x, crop_y, bias, out);
}